// round 2
// baseline (speedup 1.0000x reference)
#include <cuda_runtime.h>
#include <cstddef>

// Problem: RecurrentLinearAttentionPPLM
// Shapes: N=32, H=16 -> NH=512 ; D=M=64 ; T=2048, T1=2049
// Inputs (metadata order): query[N,H,D], key[N,H,D], value[N,H,M],
//                          k_hist[N,H,D,T], v_hist[N,H,M,T]   (all f32)
// Outputs (flat concat, reference return order): V[N,H,M], K_cat[N,H,D,T+1],
//                                                V_cat[N,H,M,T+1]
//
// Reassociated math (collapses the einsum chain to streaming + dots):
//   Qf = elu(q)+1, Kf = elu(k)+1
//   s[nh,j] = sum_d Qf[nh,d] * K_cat[nh,d,j]      (j = 0..T)
//   Z[nh]   = 1 / (sum_j s[nh,j] + eps)
//   V[nh,m] = Z[nh] * sum_j s[nh,j] * V_cat[nh,m,j]

#define NH   512
#define DD   64
#define MM   64
#define TT   2048
#define T1   2049
#define T1P  2052      // padded stride for g_s (16B-aligned rows)
#define EPSF 1e-6f

__device__ float g_s[(size_t)NH * T1P];   // s[nh, j], j in [0, T]; padded
__device__ float g_z[NH];                 // 1/(Q.Zi + eps)

// ---------------------------------------------------------------------------
// Kernel K: stream k_hist -> K_cat (stride 2048 -> 2049), build s row,
//           tail column K_cat[...,T]=Kf, finalize Z[nh].
// grid = NH, block = 256 ; thread t owns j = 4t..4t+3 and 1024+4t..1024+4t+3
// ---------------------------------------------------------------------------
__global__ void __launch_bounds__(256) k_kpart(
    const float* __restrict__ q, const float* __restrict__ k,
    const float* __restrict__ kh, float* __restrict__ kcat)
{
    const int nh = blockIdx.x;
    const int t  = threadIdx.x;

    __shared__ float qf_s[DD];
    __shared__ float pk_s[DD];     // qf*kf per d, for s[T]
    __shared__ float red[256];

    const float* in  = kh   + (size_t)nh * DD * TT;
    float*       out = kcat + (size_t)nh * DD * T1;

    if (t < DD) {
        float qv = q[nh * DD + t], kv = k[nh * DD + t];
        float qf = qv > 0.f ? qv + 1.f : expf(qv);   // elu(x)+1
        float kf = kv > 0.f ? kv + 1.f : expf(kv);
        qf_s[t] = qf;
        pk_s[t] = qf * kf;
        out[(size_t)t * T1 + TT] = kf;               // K_cat tail column
    }
    __syncthreads();

    float s0[4] = {0.f, 0.f, 0.f, 0.f};
    float s1[4] = {0.f, 0.f, 0.f, 0.f};

    for (int d = 0; d < DD; d++) {
        const float  qd  = qf_s[d];
        const float4* ri = (const float4*)(in + (size_t)d * TT);
        float*        ro = out + (size_t)d * T1;

        float4 a = __ldcs(ri + t);          // j = 4t .. 4t+3
        float4 b = __ldcs(ri + 256 + t);    // j = 1024+4t ..

        __stcs(ro + 4 * t + 0, a.x);  s0[0] = fmaf(qd, a.x, s0[0]);
        __stcs(ro + 4 * t + 1, a.y);  s0[1] = fmaf(qd, a.y, s0[1]);
        __stcs(ro + 4 * t + 2, a.z);  s0[2] = fmaf(qd, a.z, s0[2]);
        __stcs(ro + 4 * t + 3, a.w);  s0[3] = fmaf(qd, a.w, s0[3]);
        __stcs(ro + 1024 + 4 * t + 0, b.x);  s1[0] = fmaf(qd, b.x, s1[0]);
        __stcs(ro + 1024 + 4 * t + 1, b.y);  s1[1] = fmaf(qd, b.y, s1[1]);
        __stcs(ro + 1024 + 4 * t + 2, b.z);  s1[2] = fmaf(qd, b.z, s1[2]);
        __stcs(ro + 1024 + 4 * t + 3, b.w);  s1[3] = fmaf(qd, b.w, s1[3]);
    }

    float4* srow4 = (float4*)(g_s + (size_t)nh * T1P);
    srow4[t]       = make_float4(s0[0], s0[1], s0[2], s0[3]);
    srow4[256 + t] = make_float4(s1[0], s1[1], s1[2], s1[3]);

    float tot = s0[0] + s0[1] + s0[2] + s0[3]
              + s1[0] + s1[1] + s1[2] + s1[3];
    red[t] = tot;
    __syncthreads();
    #pragma unroll
    for (int off = 128; off > 0; off >>= 1) {
        if (t < off) red[t] += red[t + off];
        __syncthreads();
    }
    if (t == 0) {
        float sT = 0.f;
        #pragma unroll
        for (int d = 0; d < DD; d++) sT += pk_s[d];
        g_s[(size_t)nh * T1P + TT] = sT;
        g_z[nh] = 1.f / (red[0] + sT + EPSF);
    }
}

// ---------------------------------------------------------------------------
// Kernel V: stream v_hist -> V_cat, dot with s row (L2-resident),
//           tail column V_cat[...,T]=value, write V output.
// grid = NH*MM (one block per row), block = 256
// ---------------------------------------------------------------------------
__global__ void __launch_bounds__(256) k_vpart(
    const float* __restrict__ vh, const float* __restrict__ val,
    float* __restrict__ vcat, float* __restrict__ vout)
{
    const int g  = blockIdx.x;        // nh*MM + m
    const int nh = g >> 6;
    const int t  = threadIdx.x;

    const float4* srow4 = (const float4*)(g_s + (size_t)nh * T1P);
    const float4* ri    = (const float4*)(vh + (size_t)g * TT);
    float*        ro    = vcat + (size_t)g * T1;

    float4 a  = __ldcs(ri + t);
    float4 b  = __ldcs(ri + 256 + t);
    float4 sa = srow4[t];
    float4 sb = srow4[256 + t];

    __stcs(ro + 4 * t + 0, a.x);
    __stcs(ro + 4 * t + 1, a.y);
    __stcs(ro + 4 * t + 2, a.z);
    __stcs(ro + 4 * t + 3, a.w);
    __stcs(ro + 1024 + 4 * t + 0, b.x);
    __stcs(ro + 1024 + 4 * t + 1, b.y);
    __stcs(ro + 1024 + 4 * t + 2, b.z);
    __stcs(ro + 1024 + 4 * t + 3, b.w);

    float acc = sa.x * a.x + sa.y * a.y + sa.z * a.z + sa.w * a.w
              + sb.x * b.x + sb.y * b.y + sb.z * b.z + sb.w * b.w;

    __shared__ float red[256];
    red[t] = acc;
    __syncthreads();
    #pragma unroll
    for (int off = 128; off > 0; off >>= 1) {
        if (t < off) red[t] += red[t + off];
        __syncthreads();
    }
    if (t == 0) {
        float vlast = val[g];
        ro[TT] = vlast;                                 // V_cat tail column
        float sT = g_s[(size_t)nh * T1P + TT];
        vout[g] = g_z[nh] * (red[0] + sT * vlast);
    }
}

// ---------------------------------------------------------------------------
extern "C" void kernel_launch(void* const* d_in, const int* in_sizes, int n_in,
                              void* d_out, int out_size)
{
    const float* q   = (const float*)d_in[0];  // [N,H,D]
    const float* k   = (const float*)d_in[1];  // [N,H,D]
    const float* val = (const float*)d_in[2];  // [N,H,M]
    const float* kh  = (const float*)d_in[3];  // [N,H,D,T]
    const float* vh  = (const float*)d_in[4];  // [N,H,M,T]

    float* out  = (float*)d_out;
    // flat concat of outputs in reference return order: V, K_cat, V_cat
    float* vout = out;                             // NH*MM
    float* kcat = out + (size_t)NH * MM;           // NH*DD*T1
    float* vcat = kcat + (size_t)NH * DD * T1;     // NH*MM*T1

    k_kpart<<<NH, 256>>>(q, k, kh, kcat);
    k_vpart<<<NH * MM, 256>>>(vh, val, vcat, vout);
}

// round 3
// speedup vs baseline: 1.1508x; 1.1508x over previous
#include <cuda_runtime.h>
#include <cstddef>

// RecurrentLinearAttentionPPLM — N=32,H=16 (NH=512); D=M=64; T=2048, T1=2049
// Inputs: query[NH,D], key[NH,D], value[NH,M], k_hist[NH,D,T], v_hist[NH,M,T]
// Output (flat concat): V[NH,M], K_cat[NH,D,T1], V_cat[NH,M,T1]
//
// Reassociated math:
//   Qf = elu(q)+1, Kf = elu(k)+1
//   s[nh,j] = sum_d Qf[nh,d] * K_cat[nh,d,j]
//   Z[nh]   = 1/(sum_j s[nh,j] + eps)
//   V[nh,m] = Z[nh] * sum_j s[nh,j] * V_cat[nh,m,j]
//
// Store trick: 4 consecutive output rows (stride 2049) = 8196 words =
// exactly 2049 aligned float4s -> stage 4-row group in smem, store with
// pure coalesced STG.128 (tail elements included in the span).

#define NH   512
#define TT   2048
#define T1   2049
#define T1P  2052            // padded g_s row stride (16B-aligned)
#define GRPW 8196            // words per 4-row output group
#define EPSF 1e-6f

__device__ float g_s[(size_t)NH * T1P];
__device__ float g_z[NH];

// ---------------------------------------------------------------------------
// k_kpart: block per nh. 16 groups of 4 d-rows, double-buffered loads.
// ---------------------------------------------------------------------------
__global__ void __launch_bounds__(256) k_kpart(
    const float* __restrict__ q, const float* __restrict__ k,
    const float* __restrict__ kh, float* __restrict__ kcat)
{
    __shared__ float qf_s[64];
    __shared__ float kf_s[64];
    __shared__ float stage[GRPW];
    __shared__ float red[256];

    const int nh = blockIdx.x;
    const int t  = threadIdx.x;

    const float* in   = kh   + (size_t)nh * 64 * TT;
    float*       outp = kcat + (size_t)nh * 64 * T1;

    if (t < 64) {
        float qv = q[nh * 64 + t], kv = k[nh * 64 + t];
        qf_s[t] = qv > 0.f ? qv + 1.f : expf(qv);
        kf_s[t] = kv > 0.f ? kv + 1.f : expf(kv);
    }
    __syncthreads();

    float4 A[8];
    {
        const float4* in4 = (const float4*)in;
        #pragma unroll
        for (int u = 0; u < 8; u++) A[u] = __ldcs(in4 + t + 256 * u);
    }

    float s0[4] = {0.f, 0.f, 0.f, 0.f};   // cols 4t..4t+3
    float s1[4] = {0.f, 0.f, 0.f, 0.f};   // cols 1024+4t..+3

    for (int grp = 0; grp < 16; grp++) {
        float4 B[8];
        if (grp < 15) {
            const float4* nin4 = (const float4*)(in + (size_t)(grp + 1) * 4 * TT);
            #pragma unroll
            for (int u = 0; u < 8; u++) B[u] = __ldcs(nin4 + t + 256 * u);
        }

        #pragma unroll
        for (int u = 0; u < 8; u++) {
            const int   r  = u >> 1;                 // local row 0..3
            const float qd = qf_s[grp * 4 + r];
            float4 a = A[u];
            if (u & 1) {
                s1[0] = fmaf(qd, a.x, s1[0]); s1[1] = fmaf(qd, a.y, s1[1]);
                s1[2] = fmaf(qd, a.z, s1[2]); s1[3] = fmaf(qd, a.w, s1[3]);
            } else {
                s0[0] = fmaf(qd, a.x, s0[0]); s0[1] = fmaf(qd, a.y, s0[1]);
                s0[2] = fmaf(qd, a.z, s0[2]); s0[3] = fmaf(qd, a.w, s0[3]);
            }
            const int x = r * T1 + 4 * t + (u & 1) * 1024;
            stage[x] = a.x; stage[x + 1] = a.y; stage[x + 2] = a.z; stage[x + 3] = a.w;
        }
        if (t < 4) stage[t * T1 + TT] = kf_s[grp * 4 + t];   // tail column
        __syncthreads();

        float4*       o4  = (float4*)(outp + (size_t)grp * GRPW);
        const float4* st4 = (const float4*)stage;
        #pragma unroll
        for (int u = 0; u < 8; u++) __stcs(o4 + t + 256 * u, st4[t + 256 * u]);
        if (t == 0) __stcs(o4 + 2048, st4[2048]);
        __syncthreads();

        #pragma unroll
        for (int u = 0; u < 8; u++) A[u] = B[u];
    }

    // s row + Z
    float4* srow4 = (float4*)(g_s + (size_t)nh * T1P);
    srow4[t]       = make_float4(s0[0], s0[1], s0[2], s0[3]);
    srow4[256 + t] = make_float4(s1[0], s1[1], s1[2], s1[3]);

    red[t] = s0[0] + s0[1] + s0[2] + s0[3] + s1[0] + s1[1] + s1[2] + s1[3];
    __syncthreads();
    #pragma unroll
    for (int off = 128; off > 0; off >>= 1) {
        if (t < off) red[t] += red[t + off];
        __syncthreads();
    }
    if (t == 0) {
        float sT = 0.f;
        #pragma unroll
        for (int d = 0; d < 64; d++) sT = fmaf(qf_s[d], kf_s[d], sT);
        g_s[(size_t)nh * T1P + TT] = sT;
        g_z[nh] = 1.f / (red[0] + sT + EPSF);
    }
}

// ---------------------------------------------------------------------------
// k_vpart: block per (nh, group of 4 m-rows). grid = NH*16 = 8192.
// ---------------------------------------------------------------------------
__global__ void __launch_bounds__(256) k_vpart(
    const float* __restrict__ vh, const float* __restrict__ val,
    float* __restrict__ vcat, float* __restrict__ vout)
{
    __shared__ float stage[GRPW];
    __shared__ float red[4][8];

    const int b  = blockIdx.x;
    const int nh = b >> 4;
    const int m0 = (b & 15) * 4;
    const int t  = threadIdx.x;
    const int warp = t >> 5, lane = t & 31;

    const size_t rowbase = (size_t)nh * 64 + m0;
    const float4* in4  = (const float4*)(vh + rowbase * TT);
    float*        outp = vcat + rowbase * T1;
    const float4* s4   = (const float4*)(g_s + (size_t)nh * T1P);

    float4 A[8];
    #pragma unroll
    for (int u = 0; u < 8; u++) A[u] = __ldcs(in4 + t + 256 * u);

    const float4 sa = s4[t];          // cols 4t..4t+3   (L2-resident)
    const float4 sb = s4[256 + t];    // cols 1024+4t..+3

    float acc[4] = {0.f, 0.f, 0.f, 0.f};
    #pragma unroll
    for (int u = 0; u < 8; u++) {
        const int r = u >> 1;
        const float4 sv = (u & 1) ? sb : sa;
        float4 a = A[u];
        acc[r] = fmaf(sv.x, a.x, acc[r]);
        acc[r] = fmaf(sv.y, a.y, acc[r]);
        acc[r] = fmaf(sv.z, a.z, acc[r]);
        acc[r] = fmaf(sv.w, a.w, acc[r]);
        const int x = r * T1 + 4 * t + (u & 1) * 1024;
        stage[x] = a.x; stage[x + 1] = a.y; stage[x + 2] = a.z; stage[x + 3] = a.w;
    }
    if (t < 4) stage[t * T1 + TT] = val[rowbase + t];   // tail column

    // per-row warp reduction -> red[r][warp]
    #pragma unroll
    for (int r = 0; r < 4; r++) {
        float v = acc[r];
        #pragma unroll
        for (int off = 16; off; off >>= 1)
            v += __shfl_down_sync(0xffffffffu, v, off);
        if (lane == 0) red[r][warp] = v;
    }
    __syncthreads();

    // coalesced aligned store of the whole 4-row span
    float4*       o4  = (float4*)outp;
    const float4* st4 = (const float4*)stage;
    #pragma unroll
    for (int u = 0; u < 8; u++) __stcs(o4 + t + 256 * u, st4[t + 256 * u]);
    if (t == 0) __stcs(o4 + 2048, st4[2048]);

    if (t < 4) {
        float tot = 0.f;
        #pragma unroll
        for (int w = 0; w < 8; w++) tot += red[t][w];
        const float sT    = g_s[(size_t)nh * T1P + TT];
        const float vlast = val[rowbase + t];
        vout[rowbase + t] = g_z[nh] * (tot + sT * vlast);
    }
}

// ---------------------------------------------------------------------------
extern "C" void kernel_launch(void* const* d_in, const int* in_sizes, int n_in,
                              void* d_out, int out_size)
{
    const float* q   = (const float*)d_in[0];
    const float* k   = (const float*)d_in[1];
    const float* val = (const float*)d_in[2];
    const float* kh  = (const float*)d_in[3];
    const float* vh  = (const float*)d_in[4];

    float* out  = (float*)d_out;
    float* vout = out;                              // NH*64
    float* kcat = out + (size_t)NH * 64;            // NH*64*T1
    float* vcat = kcat + (size_t)NH * 64 * T1;      // NH*64*T1

    k_kpart<<<NH, 256>>>(q, k, kh, kcat);
    k_vpart<<<NH * 16, 256>>>(vh, val, vcat, vout);
}

// round 4
// speedup vs baseline: 1.1580x; 1.0063x over previous
#include <cuda_runtime.h>
#include <cstddef>

// RecurrentLinearAttentionPPLM — NH=512; D=M=64; T=2048, T1=2049
// Inputs: query[NH,64], key[NH,64], value[NH,64], k_hist[NH,64,T], v_hist[NH,64,T]
// Output (flat concat): V[NH,64], K_cat[NH,64,T1], V_cat[NH,64,T1]
//
//   Qf = elu(q)+1, Kf = elu(k)+1
//   s[nh,j] = sum_d Qf[nh,d]*K_cat[nh,d,j] ;  Z = 1/(sum_j s + eps)
//   V[nh,m] = Z * sum_j s[nh,j]*V_cat[nh,m,j]

#define NH   512
#define TT   2048
#define T1   2049
#define T1P  2052
#define GRPW 8196
#define WCH  512          // j-chunk width for k-side
#define NCH  4
#define EPSF 1e-6f

__device__ float g_qf[NH * 64];
__device__ float g_s [(size_t)NH * T1P];     // s row (tail at index TT)
__device__ float g_zp[NH * NCH];             // per-chunk partial of sum_j s

// ---------------------------------------------------------------------------
// prep: feature maps, tail columns, sT term.  grid=NH, block=64
// ---------------------------------------------------------------------------
__global__ void __launch_bounds__(64) k_prep(
    const float* __restrict__ q, const float* __restrict__ k,
    const float* __restrict__ val,
    float* __restrict__ kcat, float* __restrict__ vcat)
{
    const int nh = blockIdx.x, t = threadIdx.x;
    const int idx = nh * 64 + t;

    float qv = q[idx], kv = k[idx];
    float qf = qv > 0.f ? qv + 1.f : expf(qv);
    float kf = kv > 0.f ? kv + 1.f : expf(kv);

    g_qf[idx] = qf;
    kcat[(size_t)idx * T1 + TT] = kf;
    vcat[(size_t)idx * T1 + TT] = val[idx];

    float p = qf * kf;
    #pragma unroll
    for (int off = 16; off; off >>= 1) p += __shfl_down_sync(0xffffffffu, p, off);
    __shared__ float w[2];
    if ((t & 31) == 0) w[t >> 5] = p;
    __syncthreads();
    if (t == 0) g_s[(size_t)nh * T1P + TT] = w[0] + w[1];   // sT
}

// ---------------------------------------------------------------------------
// k_kpart: block per (nh, j-chunk). 64 d-rows, double-buffered staging,
// spread-word coalesced STG.32 stores (misalignment-proof). grid=NH*NCH.
// ---------------------------------------------------------------------------
__global__ void __launch_bounds__(128) k_kpart(
    const float* __restrict__ kh, float* __restrict__ kcat)
{
    __shared__ float qf_s[64];
    __shared__ __align__(16) float stage[2][WCH];
    __shared__ float red[4];

    const int b  = blockIdx.x;
    const int nh = b >> 2;
    const int j0 = (b & 3) * WCH;
    const int t  = threadIdx.x;

    if (t < 64) qf_s[t] = g_qf[nh * 64 + t];
    __syncthreads();

    const float* in      = kh   + (size_t)nh * 64 * TT + j0;
    float*       outbase = kcat + (size_t)nh * 64 * T1 + j0;

    float4 A = __ldcs((const float4*)in + t);
    float s0 = 0.f, s1 = 0.f, s2 = 0.f, s3 = 0.f;

    for (int d = 0; d < 64; d++) {
        float4 B;
        if (d < 63) B = __ldcs((const float4*)(in + (size_t)(d + 1) * TT) + t);

        const float qd = qf_s[d];
        s0 = fmaf(qd, A.x, s0); s1 = fmaf(qd, A.y, s1);
        s2 = fmaf(qd, A.z, s2); s3 = fmaf(qd, A.w, s3);

        float* st = stage[d & 1];
        ((float4*)st)[t] = A;
        __syncthreads();

        float* o = outbase + (size_t)d * T1;
        __stcs(o + t,       st[t]);
        __stcs(o + t + 128, st[t + 128]);
        __stcs(o + t + 256, st[t + 256]);
        __stcs(o + t + 384, st[t + 384]);

        A = B;
    }

    // s chunk (thread-local, aligned float4 store)
    ((float4*)(g_s + (size_t)nh * T1P + j0))[t] = make_float4(s0, s1, s2, s3);

    // per-chunk partial of sum_j s  (deterministic, no atomics)
    float v = s0 + s1 + s2 + s3;
    #pragma unroll
    for (int off = 16; off; off >>= 1) v += __shfl_down_sync(0xffffffffu, v, off);
    if ((t & 31) == 0) red[t >> 5] = v;
    __syncthreads();
    if (t == 0) g_zp[nh * NCH + (b & 3)] = red[0] + red[1] + red[2] + red[3];
}

// ---------------------------------------------------------------------------
// k_vpart: block per (nh, 4-row group); contiguous STG.128 span. grid=NH*16.
// ---------------------------------------------------------------------------
__global__ void __launch_bounds__(256) k_vpart(
    const float* __restrict__ vh, const float* __restrict__ val,
    float* __restrict__ vcat, float* __restrict__ vout)
{
    __shared__ float stage[GRPW];
    __shared__ float red[4][8];

    const int b  = blockIdx.x;
    const int nh = b >> 4;
    const int m0 = (b & 15) * 4;
    const int t  = threadIdx.x;
    const int warp = t >> 5, lane = t & 31;

    const size_t rowbase = (size_t)nh * 64 + m0;
    const float4* in4  = (const float4*)(vh + rowbase * TT);
    float*        outp = vcat + rowbase * T1;
    const float4* s4   = (const float4*)(g_s + (size_t)nh * T1P);

    float4 A[8];
    #pragma unroll
    for (int u = 0; u < 8; u++) A[u] = __ldcs(in4 + t + 256 * u);

    const float4 sa = s4[t];
    const float4 sb = s4[256 + t];

    float acc[4] = {0.f, 0.f, 0.f, 0.f};
    #pragma unroll
    for (int u = 0; u < 8; u++) {
        const int r = u >> 1;
        const float4 sv = (u & 1) ? sb : sa;
        float4 a = A[u];
        acc[r] = fmaf(sv.x, a.x, acc[r]);
        acc[r] = fmaf(sv.y, a.y, acc[r]);
        acc[r] = fmaf(sv.z, a.z, acc[r]);
        acc[r] = fmaf(sv.w, a.w, acc[r]);
        const int x = r * T1 + 4 * t + (u & 1) * 1024;
        stage[x] = a.x; stage[x + 1] = a.y; stage[x + 2] = a.z; stage[x + 3] = a.w;
    }
    if (t < 4) stage[t * T1 + TT] = val[rowbase + t];

    #pragma unroll
    for (int r = 0; r < 4; r++) {
        float v = acc[r];
        #pragma unroll
        for (int off = 16; off; off >>= 1) v += __shfl_down_sync(0xffffffffu, v, off);
        if (lane == 0) red[r][warp] = v;
    }
    __syncthreads();

    float4*       o4  = (float4*)outp;
    const float4* st4 = (const float4*)stage;
    #pragma unroll
    for (int u = 0; u < 8; u++) __stcs(o4 + t + 256 * u, st4[t + 256 * u]);
    if (t == 0) __stcs(o4 + 2048, st4[2048]);

    if (t < 4) {
        float tot = 0.f;
        #pragma unroll
        for (int w = 0; w < 8; w++) tot += red[t][w];
        const float sT    = g_s[(size_t)nh * T1P + TT];
        const float vlast = val[rowbase + t];
        const float zsum  = g_zp[nh * NCH + 0] + g_zp[nh * NCH + 1]
                          + g_zp[nh * NCH + 2] + g_zp[nh * NCH + 3] + sT;
        vout[rowbase + t] = (tot + sT * vlast) / (zsum + EPSF);
    }
}

// ---------------------------------------------------------------------------
extern "C" void kernel_launch(void* const* d_in, const int* in_sizes, int n_in,
                              void* d_out, int out_size)
{
    const float* q   = (const float*)d_in[0];
    const float* k   = (const float*)d_in[1];
    const float* val = (const float*)d_in[2];
    const float* kh  = (const float*)d_in[3];
    const float* vh  = (const float*)d_in[4];

    float* out  = (float*)d_out;
    float* vout = out;
    float* kcat = out + (size_t)NH * 64;
    float* vcat = kcat + (size_t)NH * 64 * T1;

    k_prep <<<NH, 64>>>(q, k, val, kcat, vcat);
    k_kpart<<<NH * NCH, 128>>>(kh, kcat);
    k_vpart<<<NH * 16, 256>>>(vh, val, vcat, vout);
}